// round 9
// baseline (speedup 1.0000x reference)
#include <cuda_runtime.h>
#include <cuda_fp16.h>
#include <math.h>
#include <stdint.h>

#define N_NODES 50000
#define N_EDGES 800000
#define HEADS 2
#define HID 64
#define FDIM 128
#define ODIM 128  // HEADS*HID

#define CAP 96                   // bucket capacity per node (deg ~ Poisson(16))
#define GEMM_BLKS 782            // ceil(50000/64)
#define SCAT_BLKS 782            // ceil(800000/1024)

// ---------------- scratch (device globals; no allocation allowed) ----------
__device__ __half2 d_xsh[N_NODES * 64];     // xs in fp16 (64 half2 per node)
__device__ float d_asrc[N_NODES * HEADS];
__device__ float d_adst[N_NODES * HEADS];
__device__ float d_vdst[HEADS * FDIM];      // W_dst[:,h-block] @ att_dst[h]
__device__ int   d_is64;                    // edge_index dtype flag

// zero at module load; k_agg re-zeroes after use so every call starts clean
__device__ int d_deg[N_NODES];
__device__ int d_csr[N_NODES * CAP];        // bucketed src ids (no scan needed)

// ---------------- helpers ----------------
__device__ __forceinline__ int2 load_edge(const void* ei, int i) {
    if (d_is64) {
        const long long* p = (const long long*)ei;
        return make_int2((int)p[i], (int)p[N_EDGES + i]);
    } else {
        const int* p = (const int*)ei;
        return make_int2(p[i], p[N_EDGES + i]);
    }
}

// ---------------- pre: v_dst (warp-parallel) + dtype detect ----------------
// grid = 9 blocks x 256. Blocks 0-7: v_dst (64 warps x 4 outputs). Block 8: detect.
__global__ void k_pre(const void* ei, const float* __restrict__ Wd,
                      const float* __restrict__ attd) {
    int b = blockIdx.x;
    int tid = threadIdx.x;
    if (b == 8) {
        if (tid == 0) {
            const unsigned long long* p = (const unsigned long long*)ei;
            int is64 = 1;
            for (int j = 0; j < 8; j++)
                if (p[j] >= (unsigned long long)N_NODES) is64 = 0;
            d_is64 = is64;
        }
        return;
    }
    int lane = tid & 31;
    int w = b * 8 + (tid >> 5);          // global warp 0..63
#pragma unroll
    for (int o = 0; o < 4; o++) {
        int idx = w * 4 + o;             // output 0..255
        int h = idx >> 7;
        int k = idx & 127;
        float s = Wd[k * ODIM + h * HID + lane]      * attd[h * HID + lane]
                + Wd[k * ODIM + h * HID + 32 + lane] * attd[h * HID + 32 + lane];
#pragma unroll
        for (int off = 16; off; off >>= 1) s += __shfl_down_sync(0xffffffffu, s, off);
        if (lane == 0) d_vdst[idx] = s;
    }
}

// ---------------- fat kernel: GEMM(+a_src,+a_dst) blocks ∥ bucket scatter --
// GEMM: 64 nodes x 128 cols per block, 256 threads, thread tile 8x4.
// (single-buffered — R8's double-buffer regressed via register pressure)
__global__ void __launch_bounds__(256) k_fat(const float* __restrict__ x,
                                             const float* __restrict__ W,
                                             const float* __restrict__ att_src,
                                             const void* __restrict__ ei) {
    if (blockIdx.x >= GEMM_BLKS) {
        // ---- scatter branch: 1024 edges per block, 4 per thread ----
        int base = (blockIdx.x - GEMM_BLKS) * 1024 + threadIdx.x;
#pragma unroll
        for (int s = 0; s < 4; s++) {
            int i = base + s * 256;
            if (i < N_EDGES) {
                int2 e = load_edge(ei, i);
                int pos = atomicAdd(&d_deg[e.y], 1);
                if (pos < CAP) d_csr[e.y * CAP + pos] = e.x;
            }
        }
        return;
    }

    // ---- GEMM branch ----
    __shared__ float xT[16][64];      // [k][node]
    __shared__ float w_sh[16][128];   // [k][col]
    __shared__ float vs[2 * FDIM];    // v_dst
    __shared__ float red[256];        // a_dst reduction
    const int tid = threadIdx.x;
    const int cg = tid & 31;   // column group (4 cols)
    const int ng = tid >> 5;   // node group (8 nodes)
    const int nodeBase = blockIdx.x * 64;

    vs[tid] = d_vdst[tid];            // 256 = 2*128 floats

    float4 acc[8];
#pragma unroll
    for (int i = 0; i < 8; i++) acc[i] = make_float4(0.f, 0.f, 0.f, 0.f);

    // a_dst partial: thread covers (node2 = tid&63, h2 = (tid>>6)&1, khalf = tid>>7)
    const int node2 = tid & 63;
    const int h2 = (tid >> 6) & 1;
    const int khalf = tid >> 7;
    float sdst = 0.0f;

#pragma unroll 1
    for (int kc = 0; kc < FDIM; kc += 16) {
        {
            int n = tid & 63;
            int kq = tid >> 6;           // 0..3
            int gn = nodeBase + n;
            float4 v = make_float4(0.f, 0.f, 0.f, 0.f);
            if (gn < N_NODES) v = *(const float4*)&x[gn * FDIM + kc + kq * 4];
            xT[kq * 4 + 0][n] = v.x;
            xT[kq * 4 + 1][n] = v.y;
            xT[kq * 4 + 2][n] = v.z;
            xT[kq * 4 + 3][n] = v.w;
        }
#pragma unroll
        for (int s = 0; s < 2; s++) {
            int slot = tid + s * 256;
            int r = slot >> 5;
            int c4 = slot & 31;
            *(float4*)&w_sh[r][c4 * 4] = *(const float4*)&W[(kc + r) * ODIM + c4 * 4];
        }
        __syncthreads();
#pragma unroll
        for (int k = 0; k < 16; k++) {
            float4 b = *(float4*)&w_sh[k][cg * 4];
            float4 alo = *(float4*)&xT[k][ng * 8];
            float4 ahi = *(float4*)&xT[k][ng * 8 + 4];
            acc[0].x += alo.x * b.x; acc[0].y += alo.x * b.y; acc[0].z += alo.x * b.z; acc[0].w += alo.x * b.w;
            acc[1].x += alo.y * b.x; acc[1].y += alo.y * b.y; acc[1].z += alo.y * b.z; acc[1].w += alo.y * b.w;
            acc[2].x += alo.z * b.x; acc[2].y += alo.z * b.y; acc[2].z += alo.z * b.z; acc[2].w += alo.z * b.w;
            acc[3].x += alo.w * b.x; acc[3].y += alo.w * b.y; acc[3].z += alo.w * b.z; acc[3].w += alo.w * b.w;
            acc[4].x += ahi.x * b.x; acc[4].y += ahi.x * b.y; acc[4].z += ahi.x * b.z; acc[4].w += ahi.x * b.w;
            acc[5].x += ahi.y * b.x; acc[5].y += ahi.y * b.y; acc[5].z += ahi.y * b.z; acc[5].w += ahi.y * b.w;
            acc[6].x += ahi.z * b.x; acc[6].y += ahi.z * b.y; acc[6].z += ahi.z * b.z; acc[6].w += ahi.z * b.w;
            acc[7].x += ahi.w * b.x; acc[7].y += ahi.w * b.y; acc[7].z += ahi.w * b.z; acc[7].w += ahi.w * b.w;
        }
        // fused a_dst partials: 8 FMA per thread
#pragma unroll
        for (int k = 0; k < 8; k++) {
            int kk = khalf * 8 + k;
            sdst += xT[kk][node2] * vs[h2 * FDIM + kc + kk];
        }
        __syncthreads();
    }

    // a_dst reduction: pair (tid, tid+128) → d_adst
    red[tid] = sdst;
    __syncthreads();
    if (tid < 128) {
        int gn = nodeBase + node2;
        if (gn < N_NODES) d_adst[gn * 2 + h2] = red[tid] + red[tid + 128];
    }

    // epilogue: fp16 xs store + fused a_src partial reduce
    const int h = cg >> 4;
    float4 as4 = *(const float4*)&att_src[h * HID + (cg & 15) * 4];
#pragma unroll
    for (int i = 0; i < 8; i++) {
        int row = nodeBase + ng * 8 + i;
        bool ok = row < N_NODES;
        if (ok) {
            union { __half2 h2v[2]; uint2 u; } pk;
            pk.h2v[0] = __floats2half2_rn(acc[i].x, acc[i].y);
            pk.h2v[1] = __floats2half2_rn(acc[i].z, acc[i].w);
            *(uint2*)&d_xsh[row * 64 + cg * 2] = pk.u;
        }
        float part = acc[i].x * as4.x + acc[i].y * as4.y + acc[i].z * as4.z + acc[i].w * as4.w;
#pragma unroll
        for (int o = 8; o; o >>= 1) part += __shfl_down_sync(0xffffffffu, part, o, 16);
        if ((cg & 15) == 0 && ok) d_asrc[row * 2 + h] = part;
    }
}

// ---------------- aggregation: warp per dst node, single-pass softmax ------
// exp args are bounded (|a| << 88) so the max-shift is an identity; skip it.
// Self-cleaning: zero d_deg[node] after reading so the next replay starts clean.
__global__ void __launch_bounds__(256) k_agg(float* __restrict__ out,
                                             const float* __restrict__ bias,
                                             const float* __restrict__ pw) {
    int node = (blockIdx.x * blockDim.x + threadIdx.x) >> 5;
    int lane = threadIdx.x & 31;
    if (node >= N_NODES) return;
    int h = lane >> 4;

    int beg = node * CAP;
    int deg = d_deg[node];
    if (lane == 0) d_deg[node] = 0;      // clean for next call
    if (deg > CAP) deg = CAP;
    float adst = d_adst[node * 2 + h];

    float den = 0.0f;
    float4 acc = make_float4(0.f, 0.f, 0.f, 0.f);
    const uint2* xh = (const uint2*)d_xsh;
#pragma unroll 4
    for (int j = 0; j < deg; j++) {
        int src = d_csr[beg + j];
        float v = d_asrc[src * 2 + h] + adst;
        v = v >= 0.0f ? v : 0.2f * v;
        float w = __expf(v);
        den += w;
        uint2 raw = xh[src * 32 + lane];
        __half2 h01 = *(__half2*)&raw.x;
        __half2 h23 = *(__half2*)&raw.y;
        float2 f0 = __half22float2(h01);
        float2 f1 = __half22float2(h23);
        acc.x += w * f0.x;
        acc.y += w * f0.y;
        acc.z += w * f1.x;
        acc.w += w * f1.y;
    }

    float inv = 1.0f / (den + 1e-16f);
    int c = lane * 4;
    float4 b = *(const float4*)&bias[c];
    float4 p = *(const float4*)&pw[c];
    float4 o;
    o.x = acc.x * inv + b.x;  o.x = o.x >= 0.0f ? o.x : p.x * o.x;
    o.y = acc.y * inv + b.y;  o.y = o.y >= 0.0f ? o.y : p.y * o.y;
    o.z = acc.z * inv + b.z;  o.z = o.z >= 0.0f ? o.z : p.z * o.z;
    o.w = acc.w * inv + b.w;  o.w = o.w >= 0.0f ? o.w : p.w * o.w;
    *(float4*)&out[(size_t)node * ODIM + c] = o;
}

// ---------------- launcher (single stream; 3 kernels total) ----------------
extern "C" void kernel_launch(void* const* d_in, const int* in_sizes, int n_in,
                              void* d_out, int out_size) {
    const float* x     = (const float*)d_in[0];
    const float* Ws    = (const float*)d_in[1];
    const float* Wd    = (const float*)d_in[2];
    const float* att_s = (const float*)d_in[3];
    const float* att_d = (const float*)d_in[4];
    const float* bias  = (const float*)d_in[5];
    const float* pw    = (const float*)d_in[6];
    const void*  ei    = d_in[7];
    float* out = (float*)d_out;

    k_pre<<<9, 256>>>(ei, Wd, att_d);
    k_fat<<<GEMM_BLKS + SCAT_BLKS, 256>>>(x, Ws, att_s, ei);
    k_agg<<<(N_NODES * 32 + 255) / 256, 256>>>(out, bias, pw);
}

// round 10
// speedup vs baseline: 1.8646x; 1.8646x over previous
#include <cuda_runtime.h>
#include <cuda_fp16.h>
#include <math.h>
#include <stdint.h>

#define N_NODES 50000
#define N_EDGES 800000
#define HEADS 2
#define HID 64
#define FDIM 128
#define ODIM 128  // HEADS*HID

#define CAP 96                   // bucket capacity per node (deg ~ Poisson(16))
#define GEMM_BLKS 782            // ceil(50000/64)
#define SCAT_BLKS 782            // ceil(800000/1024)

// ---------------- scratch (device globals; no allocation allowed) ----------
__device__ __half2 d_xsh[N_NODES * 64];     // xs in fp16 (64 half2 per node)
__device__ float d_asrc[N_NODES * HEADS];
__device__ float d_adst[N_NODES * HEADS];
__device__ float d_vdst[HEADS * FDIM];      // W_dst[:,h-block] @ att_dst[h]
__device__ int   d_is64;                    // edge_index dtype flag

__device__ int d_deg[N_NODES];              // atomic cursors == final degrees
__device__ int d_csr[N_NODES * CAP];        // bucketed src ids (no scan needed)

// ---------------- helpers ----------------
__device__ __forceinline__ int2 load_edge(const void* ei, int i) {
    if (d_is64) {
        const long long* p = (const long long*)ei;
        return make_int2((int)p[i], (int)p[N_EDGES + i]);
    } else {
        const int* p = (const int*)ei;
        return make_int2(p[i], p[N_EDGES + i]);
    }
}

// ---------------- pre: zero degrees, detect dtype, warp-parallel v_dst -----
// grid = 204: blocks 0-195 zero d_deg (+detect in block 0);
// blocks 196-203: v_dst, 8 warps/block x 4 outputs/warp.
__global__ void k_pre(const void* ei, const float* __restrict__ Wd,
                      const float* __restrict__ attd) {
    int b = blockIdx.x;
    int tid = threadIdx.x;
    if (b < 196) {
        int i = b * 256 + tid;
        if (i < N_NODES) d_deg[i] = 0;
        if (b == 0 && tid == 0) {
            const unsigned long long* p = (const unsigned long long*)ei;
            int is64 = 1;
            for (int j = 0; j < 8; j++)
                if (p[j] >= (unsigned long long)N_NODES) is64 = 0;
            d_is64 = is64;
        }
        return;
    }
    int lane = tid & 31;
    int w = (b - 196) * 8 + (tid >> 5);  // global warp 0..63
#pragma unroll
    for (int o = 0; o < 4; o++) {
        int idx = w * 4 + o;             // output 0..255
        int h = idx >> 7;
        int k = idx & 127;
        float s = Wd[k * ODIM + h * HID + lane]      * attd[h * HID + lane]
                + Wd[k * ODIM + h * HID + 32 + lane] * attd[h * HID + 32 + lane];
#pragma unroll
        for (int off = 16; off; off >>= 1) s += __shfl_down_sync(0xffffffffu, s, off);
        if (lane == 0) d_vdst[idx] = s;
    }
}

// ---------------- fat kernel: GEMM(+a_src,+a_dst) blocks ∥ bucket scatter --
// GEMM: 64 nodes x 128 cols per block, 256 threads, thread tile 8x4.
__global__ void __launch_bounds__(256) k_fat(const float* __restrict__ x,
                                             const float* __restrict__ W,
                                             const float* __restrict__ att_src,
                                             const void* __restrict__ ei) {
    if (blockIdx.x >= GEMM_BLKS) {
        // ---- scatter branch: 1024 edges per block, 4 per thread ----
        int base = (blockIdx.x - GEMM_BLKS) * 1024 + threadIdx.x;
#pragma unroll
        for (int s = 0; s < 4; s++) {
            int i = base + s * 256;
            if (i < N_EDGES) {
                int2 e = load_edge(ei, i);
                int pos = atomicAdd(&d_deg[e.y], 1);
                if (pos < CAP) d_csr[e.y * CAP + pos] = e.x;
            }
        }
        return;
    }

    // ---- GEMM branch ----
    __shared__ float xT[16][64];      // [k][node]
    __shared__ float w_sh[16][128];   // [k][col]
    __shared__ float vs[2 * FDIM];    // v_dst
    __shared__ float red[256];        // a_dst reduction
    const int tid = threadIdx.x;
    const int cg = tid & 31;   // column group (4 cols)
    const int ng = tid >> 5;   // node group (8 nodes)
    const int nodeBase = blockIdx.x * 64;

    vs[tid] = d_vdst[tid];            // 256 = 2*128 floats

    float4 acc[8];
#pragma unroll
    for (int i = 0; i < 8; i++) acc[i] = make_float4(0.f, 0.f, 0.f, 0.f);

    // a_dst partial: thread covers (node2 = tid&63, h2 = (tid>>6)&1, khalf = tid>>7)
    const int node2 = tid & 63;
    const int h2 = (tid >> 6) & 1;
    const int khalf = tid >> 7;
    float sdst = 0.0f;

#pragma unroll 1
    for (int kc = 0; kc < FDIM; kc += 16) {
        {
            int n = tid & 63;
            int kq = tid >> 6;           // 0..3
            int gn = nodeBase + n;
            float4 v = make_float4(0.f, 0.f, 0.f, 0.f);
            if (gn < N_NODES) v = *(const float4*)&x[gn * FDIM + kc + kq * 4];
            xT[kq * 4 + 0][n] = v.x;
            xT[kq * 4 + 1][n] = v.y;
            xT[kq * 4 + 2][n] = v.z;
            xT[kq * 4 + 3][n] = v.w;
        }
#pragma unroll
        for (int s = 0; s < 2; s++) {
            int slot = tid + s * 256;
            int r = slot >> 5;
            int c4 = slot & 31;
            *(float4*)&w_sh[r][c4 * 4] = *(const float4*)&W[(kc + r) * ODIM + c4 * 4];
        }
        __syncthreads();
#pragma unroll
        for (int k = 0; k < 16; k++) {
            float4 b = *(float4*)&w_sh[k][cg * 4];
            float4 alo = *(float4*)&xT[k][ng * 8];
            float4 ahi = *(float4*)&xT[k][ng * 8 + 4];
            acc[0].x += alo.x * b.x; acc[0].y += alo.x * b.y; acc[0].z += alo.x * b.z; acc[0].w += alo.x * b.w;
            acc[1].x += alo.y * b.x; acc[1].y += alo.y * b.y; acc[1].z += alo.y * b.z; acc[1].w += alo.y * b.w;
            acc[2].x += alo.z * b.x; acc[2].y += alo.z * b.y; acc[2].z += alo.z * b.z; acc[2].w += alo.z * b.w;
            acc[3].x += alo.w * b.x; acc[3].y += alo.w * b.y; acc[3].z += alo.w * b.z; acc[3].w += alo.w * b.w;
            acc[4].x += ahi.x * b.x; acc[4].y += ahi.x * b.y; acc[4].z += ahi.x * b.z; acc[4].w += ahi.x * b.w;
            acc[5].x += ahi.y * b.x; acc[5].y += ahi.y * b.y; acc[5].z += ahi.y * b.z; acc[5].w += ahi.y * b.w;
            acc[6].x += ahi.z * b.x; acc[6].y += ahi.z * b.y; acc[6].z += ahi.z * b.z; acc[6].w += ahi.z * b.w;
            acc[7].x += ahi.w * b.x; acc[7].y += ahi.w * b.y; acc[7].z += ahi.w * b.z; acc[7].w += ahi.w * b.w;
        }
        // fused a_dst partials: 8 FMA per thread
#pragma unroll
        for (int k = 0; k < 8; k++) {
            int kk = khalf * 8 + k;
            sdst += xT[kk][node2] * vs[h2 * FDIM + kc + kk];
        }
        __syncthreads();
    }

    // a_dst reduction: pair (tid, tid+128) → d_adst
    red[tid] = sdst;
    __syncthreads();
    if (tid < 128) {
        int gn = nodeBase + node2;
        if (gn < N_NODES) d_adst[gn * 2 + h2] = red[tid] + red[tid + 128];
    }

    // epilogue: fp16 xs store + fused a_src partial reduce
    const int h = cg >> 4;
    float4 as4 = *(const float4*)&att_src[h * HID + (cg & 15) * 4];
#pragma unroll
    for (int i = 0; i < 8; i++) {
        int row = nodeBase + ng * 8 + i;
        bool ok = row < N_NODES;
        if (ok) {
            union { __half2 h2v[2]; uint2 u; } pk;
            pk.h2v[0] = __floats2half2_rn(acc[i].x, acc[i].y);
            pk.h2v[1] = __floats2half2_rn(acc[i].z, acc[i].w);
            *(uint2*)&d_xsh[row * 64 + cg * 2] = pk.u;
        }
        float part = acc[i].x * as4.x + acc[i].y * as4.y + acc[i].z * as4.z + acc[i].w * as4.w;
#pragma unroll
        for (int o = 8; o; o >>= 1) part += __shfl_down_sync(0xffffffffu, part, o, 16);
        if ((cg & 15) == 0 && ok) d_asrc[row * 2 + h] = part;
    }
}

// ---------------- aggregation: warp per dst node, single-pass softmax ------
// exp args are bounded (|a| << 88) so the max-shift is an identity; skip it.
__global__ void __launch_bounds__(256) k_agg(float* __restrict__ out,
                                             const float* __restrict__ bias,
                                             const float* __restrict__ pw) {
    int node = (blockIdx.x * blockDim.x + threadIdx.x) >> 5;
    int lane = threadIdx.x & 31;
    if (node >= N_NODES) return;
    int h = lane >> 4;

    int beg = node * CAP;
    int deg = d_deg[node];
    if (deg > CAP) deg = CAP;
    float adst = d_adst[node * 2 + h];

    float den = 0.0f;
    float4 acc = make_float4(0.f, 0.f, 0.f, 0.f);
    const uint2* xh = (const uint2*)d_xsh;
#pragma unroll 4
    for (int j = 0; j < deg; j++) {
        int src = d_csr[beg + j];
        float v = d_asrc[src * 2 + h] + adst;
        v = v >= 0.0f ? v : 0.2f * v;
        float w = __expf(v);
        den += w;
        uint2 raw = xh[src * 32 + lane];
        __half2 h01 = *(__half2*)&raw.x;
        __half2 h23 = *(__half2*)&raw.y;
        float2 f0 = __half22float2(h01);
        float2 f1 = __half22float2(h23);
        acc.x += w * f0.x;
        acc.y += w * f0.y;
        acc.z += w * f1.x;
        acc.w += w * f1.y;
    }

    float inv = 1.0f / (den + 1e-16f);
    int c = lane * 4;
    float4 b = *(const float4*)&bias[c];
    float4 p = *(const float4*)&pw[c];
    float4 o;
    o.x = acc.x * inv + b.x;  o.x = o.x >= 0.0f ? o.x : p.x * o.x;
    o.y = acc.y * inv + b.y;  o.y = o.y >= 0.0f ? o.y : p.y * o.y;
    o.z = acc.z * inv + b.z;  o.z = o.z >= 0.0f ? o.z : p.z * o.z;
    o.w = acc.w * inv + b.w;  o.w = o.w >= 0.0f ? o.w : p.w * o.w;
    *(float4*)&out[(size_t)node * ODIM + c] = o;
}

// ---------------- launcher (single stream; 3 kernels total) ----------------
extern "C" void kernel_launch(void* const* d_in, const int* in_sizes, int n_in,
                              void* d_out, int out_size) {
    const float* x     = (const float*)d_in[0];
    const float* Ws    = (const float*)d_in[1];
    const float* Wd    = (const float*)d_in[2];
    const float* att_s = (const float*)d_in[3];
    const float* att_d = (const float*)d_in[4];
    const float* bias  = (const float*)d_in[5];
    const float* pw    = (const float*)d_in[6];
    const void*  ei    = d_in[7];
    float* out = (float*)d_out;

    k_pre<<<204, 256>>>(ei, Wd, att_d);
    k_fat<<<GEMM_BLKS + SCAT_BLKS, 256>>>(x, Ws, att_s, ei);
    k_agg<<<(N_NODES * 32 + 255) / 256, 256>>>(out, bias, pw);
}